// round 17
// baseline (speedup 1.0000x reference)
#include <cuda_runtime.h>
#include <cuda_fp16.h>
#include <cstdint>

typedef unsigned long long u64;
typedef unsigned int u32;

#define NTOK 64
#define NHEAD 8
#define PSA_SCALE 0.17677669529663687f
#define NWIN 4096

// ---------------------------------------------------------------------------
// Device scratch
// ---------------------------------------------------------------------------
__device__ __half g_qkvh[(size_t)NWIN * NTOK * 384];       // 201 MB qkv fp16
__device__ __half g_w1h[384 * 256];                        // fp16 weights (q rows pre-scaled)
__device__ __half g_w2h[256 * 128];
__device__ float  g_b1[384];                               // q part pre-scaled
__device__ float  g_cmb[64 * NHEAD * NTOK * NTOK];         // bias+mask, FRAGMENT-PERMUTED cols

// ---------------------------------------------------------------------------
// Helpers
// ---------------------------------------------------------------------------
__device__ __forceinline__ u32 smem_u32(const void* p) {
    u32 a;
    asm("{ .reg .u64 t; cvta.to.shared.u64 t, %1; cvt.u32.u64 %0, t; }"
        : "=r"(a) : "l"(p));
    return a;
}
__device__ __forceinline__ void ldsm4(u32* r, u32 addr) {
    asm volatile("ldmatrix.sync.aligned.m8n8.x4.shared.b16 {%0,%1,%2,%3}, [%4];"
                 : "=r"(r[0]), "=r"(r[1]), "=r"(r[2]), "=r"(r[3]) : "r"(addr));
}
__device__ __forceinline__ void ldsm4t(u32* r, u32 addr) {
    asm volatile("ldmatrix.sync.aligned.m8n8.x4.trans.shared.b16 {%0,%1,%2,%3}, [%4];"
                 : "=r"(r[0]), "=r"(r[1]), "=r"(r[2]), "=r"(r[3]) : "r"(addr));
}
__device__ __forceinline__ void mma_fp16(float* c, const u32* a, const u32* b) {
    asm volatile(
        "mma.sync.aligned.m16n8k16.row.col.f32.f16.f16.f32 "
        "{%0,%1,%2,%3}, {%4,%5,%6,%7}, {%8,%9}, {%0,%1,%2,%3};"
        : "+f"(c[0]), "+f"(c[1]), "+f"(c[2]), "+f"(c[3])
        : "r"(a[0]), "r"(a[1]), "r"(a[2]), "r"(a[3]), "r"(b[0]), "r"(b[1]));
}
#define CP_ASYNC16(dst, src) \
    asm volatile("cp.async.cg.shared.global [%0], [%1], 16;" :: "r"(dst), "l"(src))
#define CP_COMMIT() asm volatile("cp.async.commit_group;")
#define CP_WAIT(n)  asm volatile("cp.async.wait_group %0;" :: "n"(n))

__device__ __forceinline__ u32 h2u(__half2 v) { return *reinterpret_cast<u32*>(&v); }
__device__ __forceinline__ u32 pkh(float a, float b) {
    return h2u(__float22half2_rn(make_float2(a, b)));
}

// ---------------------------------------------------------------------------
// Small prologue: blocks [0,192) w1 | [192,256) w2 | 256 b1
// (cmb generation moved inside gemm1, overlapped with its load phase)
// ---------------------------------------------------------------------------
__global__ void psa_prep_small(
    const float* __restrict__ qw,  const float* __restrict__ kvw,
    const float* __restrict__ pw,
    const float* __restrict__ qb,  const float* __restrict__ kvb)
{
    int b = blockIdx.x, t = threadIdx.x;
    if (b < 192) {                                   // w1: 2 rows per block
        int n = b * 2 + (t >> 8), k = t & 255;
        float v = (n < 128) ? qw[n * 256 + k] * PSA_SCALE
                            : kvw[(n - 128) * 256 + k];
        g_w1h[n * 256 + k] = __float2half_rn(v);
    } else if (b < 256) {                            // w2: 4 rows per block
        int n = (b - 192) * 4 + (t >> 7), k = t & 127;
        g_w2h[n * 128 + k] = __float2half_rn(pw[n * 128 + k]);
    } else {                                         // b1
        if (t < 384)
            g_b1[t] = (t < 128) ? qb[t] * PSA_SCALE : kvb[t - 128];
    }
}

// ---------------------------------------------------------------------------
// GEMM1: qkv16[M,384] = fp16( x[M,256] @ W1[384,256]^T + b1 )
// CTA M=128, 256 thr, 6 N-chunks of 64, single W buffer, 2 CTAs/SM.
// Also builds its 1024-element slice of the permuted cmb table (overlaps
// with the chunk-0 W prefetch + A conversion).
// ---------------------------------------------------------------------------
#define PK1     264                    // padded pitch (halves) for K=256
#define OFF_W1  (128 * PK1 * 2)        // 67584
#define WBUF1   (64 * PK1 * 2)         // 33792
#define SMEM_G1 (OFF_W1 + WBUF1)       // 101376  -> 2 CTAs/SM

__global__ void __launch_bounds__(256, 2) psa_gemm1(
    const float* __restrict__ A,
    const __half* __restrict__ Whg,
    const float* __restrict__ bias,
    const float* __restrict__ bt,  const int* __restrict__ ri,
    const float* __restrict__ mask,
    __half* __restrict__ out)
{
    extern __shared__ char smem[];
    const u32 sb = smem_u32(smem);
    const int t = threadIdx.x, lane = t & 31, wid = t >> 5;
    const int m0 = (wid & 3) * 32, n0 = (wid >> 2) * 32;
    const u32 wb = sb + OFF_W1;

    // prefetch W chunk 0 (32 uint4 per 64-row chunk row)
    {
        const uint4* gsrc = (const uint4*)Whg;
#pragma unroll
        for (int i = t; i < 2048; i += 256)
            CP_ASYNC16(wb + (i >> 5) * (PK1 * 2) + (i & 31) * 16, gsrc + i);
        CP_COMMIT();
    }

    // ---- build this CTA's slice of the permuted cmb table (4 elems/thr) ----
    {
        int base = blockIdx.x * 1024 + t * 4;
#pragma unroll
        for (int u = 0; u < 4; u++) {
            int idx = base + u;
            int j = idx & 63, i = (idx >> 6) & 63, hh = (idx >> 12) & 7, nw = idx >> 15;
            int p = ((j >> 1) & 3) * 16 + (j >> 3) * 2 + (j & 1);
            g_cmb[(idx - j) + p] =
                bt[ri[i * 64 + j] * NHEAD + hh] + mask[nw * 4096 + i * 64 + j];
        }
    }

    // ---- convert A tile (128 x 256 fp32) -> fp16 ----
    {
        const float* Ag = A + (size_t)blockIdx.x * 128 * 256;
#pragma unroll 4
        for (int u = t; u < 128 * 32; u += 256) {
            int r = u >> 5, k0 = (u & 31) * 8;
            float4 a = *(const float4*)(Ag + r * 256 + k0);
            float4 b = *(const float4*)(Ag + r * 256 + k0 + 4);
            *(uint4*)(smem + r * (PK1 * 2) + k0 * 2) = make_uint4(
                pkh(a.x, a.y), pkh(a.z, a.w), pkh(b.x, b.y), pkh(b.z, b.w));
        }
    }

    u32 a_off[2], w_off[2];
#pragma unroll
    for (int mi = 0; mi < 2; mi++)
        a_off[mi] = (u32)((m0 + mi * 16 + (lane & 15)) * (PK1 * 2) + (lane >> 4) * 16);
    {
        int brow = ((lane >> 4) & 1) * 8 + (lane & 7);
        int bko  = ((lane >> 3) & 1) * 16;
#pragma unroll
        for (int nj = 0; nj < 2; nj++)
            w_off[nj] = (u32)((n0 + nj * 16 + brow) * (PK1 * 2) + bko);
    }

#pragma unroll 1
    for (int ch = 0; ch < 6; ch++) {
        CP_WAIT(0);
        __syncthreads();

        float c[2][4][4];
#pragma unroll
        for (int ni = 0; ni < 4; ni++) {
            int col = ch * 64 + n0 + ni * 8 + (lane & 3) * 2;
            float b0 = __ldg(bias + col), b1 = __ldg(bias + col + 1);
#pragma unroll
            for (int mi = 0; mi < 2; mi++) {
                c[mi][ni][0] = b0; c[mi][ni][1] = b1;
                c[mi][ni][2] = b0; c[mi][ni][3] = b1;
            }
        }

#pragma unroll 4
        for (int k0 = 0; k0 < 256; k0 += 16) {
            u32 ah[2][4], wf[2][4];
#pragma unroll
            for (int mi = 0; mi < 2; mi++) ldsm4(ah[mi], sb + a_off[mi] + k0 * 2);
#pragma unroll
            for (int nj = 0; nj < 2; nj++) ldsm4(wf[nj], wb + w_off[nj] + k0 * 2);
#pragma unroll
            for (int mi = 0; mi < 2; mi++)
#pragma unroll
                for (int nt = 0; nt < 4; nt++)
                    mma_fp16(c[mi][nt], ah[mi], &wf[nt >> 1][(nt & 1) * 2]);
        }
        __syncthreads();

        if (ch + 1 < 6) {    // refill buffer; overlaps epilogue + other CTA
            const uint4* gsrc = (const uint4*)(Whg + (size_t)(ch + 1) * 64 * 256);
#pragma unroll
            for (int i = t; i < 2048; i += 256)
                CP_ASYNC16(wb + (i >> 5) * (PK1 * 2) + (i & 31) * 16, gsrc + i);
            CP_COMMIT();
        }

        {
            int rq = lane >> 2, cq = (lane & 3) * 2;
            __half* ob = out + (size_t)blockIdx.x * 128 * 384 + ch * 64;
#pragma unroll
            for (int mi = 0; mi < 2; mi++)
#pragma unroll
                for (int ni = 0; ni < 4; ni++) {
                    int rr = m0 + mi * 16 + rq, cc = n0 + ni * 8 + cq;
                    *(u32*)(ob + rr * 384 + cc)       = pkh(c[mi][ni][0], c[mi][ni][1]);
                    *(u32*)(ob + (rr + 8) * 384 + cc) = pkh(c[mi][ni][2], c[mi][ni][3]);
                }
        }
    }
}

// ---------------------------------------------------------------------------
// Fused HMMA attention + out-projection. One window per CTA, 256 threads,
// 2 CTAs/SM. ALL q/k/v frags hoisted -> qkv smem dead before attention
// compute; W2 half1 streams into it for the whole attention phase.
// No mid-gemm2 barrier.
// smem: qkv16 [64][392] (50176, becomes W2-half1 buffer) |
//       aoh [64][136] (17408) | W2buf [128][136] (34816)
// ---------------------------------------------------------------------------
#define PQ      392
#define B_AOH   50176
#define B_W2    67584
#define PA2     136
#define SMEM_B  102400

__global__ void __launch_bounds__(256, 2) psa_attn_proj(
    const __half* __restrict__ qkvg, const float* __restrict__ cmbg,
    const __half* __restrict__ W2h,  const float* __restrict__ pb,
    float* __restrict__ out)
{
    extern __shared__ char smem[];
    const u32 sb = smem_u32(smem);
    const int t = threadIdx.x, w = blockIdx.x;
    const int lane = t & 31, wid = t >> 5;

    // group 0: qkv tile (3072 uint4)
    {
        const uint4* qg = (const uint4*)qkvg + (size_t)w * 64 * 48;
#pragma unroll
        for (int i = 0; i < 12; i++) {
            int idx = t + 256 * i;
            int row = idx / 48, g = idx % 48;
            CP_ASYNC16(sb + row * (PQ * 2) + g * 16, qg + idx);
        }
        CP_COMMIT();
    }
    // group 1: W2 rows 0-127 into the dedicated half-buffer (2048 uint4)
    {
        const uint4* gsrc = (const uint4*)W2h;
#pragma unroll
        for (int i = t; i < 2048; i += 256)
            CP_ASYNC16(sb + B_W2 + (i >> 4) * (PA2 * 2) + (i & 15) * 16, gsrc + i);
        CP_COMMIT();
    }
    CP_WAIT(1);        // qkv resident
    __syncthreads();

    // =====================================================================
    // Hoist ALL fragments: K (4), V (4), Q (4 passes) -> qkv smem is dead
    // =====================================================================
    const int h  = wid;
    const int ql = lane >> 2, qg4 = lane & 3;
    const float* cmb_h = cmbg + (((w & 63) * 8 + h) * 64) * 64;

    u32 kb[4][4], vb[4][4], qa[4][4];
    {
        int brow = ((lane >> 4) & 1) * 8 + (lane & 7);
        int bko  = ((lane >> 3) & 1) * 16;
#pragma unroll
        for (int nt2 = 0; nt2 < 4; nt2++)
            ldsm4(kb[nt2], sb + (nt2 * 16 + brow) * (PQ * 2)
                           + (128 + h * 16) * 2 + bko);
        int vrow = ((lane >> 3) & 1) * 8 + (lane & 7);
        int vcol = (lane >> 4) * 8;
#pragma unroll
        for (int kt = 0; kt < 4; kt++)
            ldsm4t(vb[kt], sb + (kt * 16 + vrow) * (PQ * 2)
                           + (256 + h * 16 + vcol) * 2);
#pragma unroll
        for (int mi = 0; mi < 4; mi++)
            ldsm4(qa[mi], sb + (mi * 16 + (lane & 15)) * (PQ * 2)
                          + h * 32 + (lane >> 4) * 16);
    }
    __syncthreads();   // all warps done with qkv smem; region is dead

    // group 2: W2 rows 128-255 stream into the dead qkv region during attention
    {
        const uint4* gsrc = (const uint4*)W2h + 2048;
#pragma unroll
        for (int i = t; i < 2048; i += 256)
            CP_ASYNC16(sb + (i >> 4) * (PA2 * 2) + (i & 15) * 16, gsrc + i);
        CP_COMMIT();
    }

    // =====================================================================
    // Attention: 4 passes of 16 rows, pure register compute
    // =====================================================================
#pragma unroll 1
    for (int mi = 0; mi < 4; mi++) {
        // S = Q K^T  (scale pre-folded into q)
        float c[8][4];
#pragma unroll
        for (int nj = 0; nj < 8; nj++) { c[nj][0]=0.f; c[nj][1]=0.f; c[nj][2]=0.f; c[nj][3]=0.f; }
#pragma unroll
        for (int nj = 0; nj < 8; nj++)
            mma_fp16(c[nj], qa[mi], &kb[nj >> 1][(nj & 1) * 2]);

        // logits = S + cmb; exp without max-shift (inline float2 bias loads)
        const int r0 = mi * 16 + ql;
        const float* cp0 = cmb_h + r0 * 64 + qg4 * 16;
        const float* cp1 = cmb_h + (r0 + 8) * 64 + qg4 * 16;
        float s0 = 0.f, s1 = 0.f;
#pragma unroll
        for (int nj = 0; nj < 8; nj++) {
            float2 b0 = __ldg((const float2*)(cp0 + nj * 2));
            float2 b1 = __ldg((const float2*)(cp1 + nj * 2));
            c[nj][0] = __expf(c[nj][0] + b0.x);
            c[nj][1] = __expf(c[nj][1] + b0.y);
            c[nj][2] = __expf(c[nj][2] + b1.x);
            c[nj][3] = __expf(c[nj][3] + b1.y);
            s0 += c[nj][0] + c[nj][1];
            s1 += c[nj][2] + c[nj][3];
        }
        s0 += __shfl_xor_sync(0xffffffff, s0, 1);
        s0 += __shfl_xor_sync(0xffffffff, s0, 2);
        s1 += __shfl_xor_sync(0xffffffff, s1, 1);
        s1 += __shfl_xor_sync(0xffffffff, s1, 2);
        float inv0 = 1.0f / s0, inv1 = 1.0f / s1;

        // O = P V
        float o[2][4];
        o[0][0]=0.f;o[0][1]=0.f;o[0][2]=0.f;o[0][3]=0.f;
        o[1][0]=0.f;o[1][1]=0.f;o[1][2]=0.f;o[1][3]=0.f;
#pragma unroll
        for (int kt = 0; kt < 4; kt++) {
            u32 pa[4];
            pa[0] = pkh(c[2*kt][0]   * inv0, c[2*kt][1]   * inv0);
            pa[1] = pkh(c[2*kt][2]   * inv1, c[2*kt][3]   * inv1);
            pa[2] = pkh(c[2*kt+1][0] * inv0, c[2*kt+1][1] * inv0);
            pa[3] = pkh(c[2*kt+1][2] * inv1, c[2*kt+1][3] * inv1);
#pragma unroll
            for (int nt = 0; nt < 2; nt++)
                mma_fp16(o[nt], pa, &vb[kt][nt * 2]);
        }

        // store O -> aoh
#pragma unroll
        for (int nt = 0; nt < 2; nt++) {
            int d0 = h * 16 + nt * 8 + qg4 * 2;
#pragma unroll
            for (int rh = 0; rh < 2; rh++) {
                u32 off = (u32)((r0 + rh * 8) * (PA2 * 2) + d0 * 2);
                *(u32*)(smem + B_AOH + off) = pkh(o[nt][rh * 2], o[nt][rh * 2 + 1]);
            }
        }
    }

    CP_WAIT(0);        // W2 half 1 resident (loaded during attention)
    __syncthreads();   // aoh + both W2 halves visible

    // =====================================================================
    // GEMM2: out[64,256] = ao[64,128] @ W2^T + pb, two 128-col halves,
    // warp tile 32x32. ph0 from B_W2, ph1 from qkv-region buffer; no
    // mid-phase barrier (everything already resident).
    // =====================================================================
    const int m0g = (wid & 1) * 32;
    const int n0g = (wid >> 1) * 32;
    u32 a_off[2];
#pragma unroll
    for (int mi = 0; mi < 2; mi++)
        a_off[mi] = (u32)(B_AOH + (m0g + mi * 16 + (lane & 15)) * (PA2 * 2)
                          + (lane >> 4) * 16);
    u32 w_off[2];
    {
        int brow = ((lane >> 4) & 1) * 8 + (lane & 7);
        int bko  = ((lane >> 3) & 1) * 16;
#pragma unroll
        for (int nj = 0; nj < 2; nj++)
            w_off[nj] = (u32)((n0g + nj * 16 + brow) * (PA2 * 2) + bko);
    }
    int rq = lane >> 2, cq = (lane & 3) * 2;
    float* ob = out + (size_t)w * 64 * 256;

#pragma unroll 1
    for (int ph = 0; ph < 2; ph++) {
        const u32 wbase = sb + (ph == 0 ? B_W2 : 0);

        float c[2][4][4];
#pragma unroll
        for (int nt = 0; nt < 4; nt++) {
            int col = ph * 128 + n0g + nt * 8 + cq;
            float b0 = __ldg(pb + col), b1 = __ldg(pb + col + 1);
#pragma unroll
            for (int mi = 0; mi < 2; mi++) {
                c[mi][nt][0] = b0; c[mi][nt][1] = b1;
                c[mi][nt][2] = b0; c[mi][nt][3] = b1;
            }
        }

#pragma unroll 4
        for (int k0 = 0; k0 < 128; k0 += 16) {
            u32 ah[2][4], wf[2][4];
#pragma unroll
            for (int mi = 0; mi < 2; mi++) ldsm4(ah[mi], sb + a_off[mi] + k0 * 2);
#pragma unroll
            for (int nj = 0; nj < 2; nj++) ldsm4(wf[nj], wbase + w_off[nj] + k0 * 2);
#pragma unroll
            for (int mi = 0; mi < 2; mi++)
#pragma unroll
                for (int nt = 0; nt < 4; nt++)
                    mma_fp16(c[mi][nt], ah[mi], &wf[nt >> 1][(nt & 1) * 2]);
        }

#pragma unroll
        for (int mi = 0; mi < 2; mi++)
#pragma unroll
            for (int nt = 0; nt < 4; nt++) {
                int rr = m0g + mi * 16 + rq, cc = ph * 128 + n0g + nt * 8 + cq;
                *(float2*)(ob + rr * 256 + cc)       = make_float2(c[mi][nt][0], c[mi][nt][1]);
                *(float2*)(ob + (rr + 8) * 256 + cc) = make_float2(c[mi][nt][2], c[mi][nt][3]);
            }
    }
}

// ---------------------------------------------------------------------------
extern "C" void kernel_launch(void* const* d_in, const int* in_sizes, int n_in,
                              void* d_out, int out_size) {
    const float* x      = (const float*)d_in[0];
    const float* mask   = (const float*)d_in[1];
    const float* q_w    = (const float*)d_in[2];
    const float* q_b    = (const float*)d_in[3];
    const float* kv_w   = (const float*)d_in[4];
    const float* kv_b   = (const float*)d_in[5];
    const float* proj_w = (const float*)d_in[6];
    const float* proj_b = (const float*)d_in[7];
    const float* bt     = (const float*)d_in[8];
    const int*   ri     = (const int*)d_in[9];
    float* out = (float*)d_out;

    void *pqkv, *pw1h, *pw2h, *pb1, *pcmb;
    cudaGetSymbolAddress(&pqkv, g_qkvh);
    cudaGetSymbolAddress(&pw1h, g_w1h);
    cudaGetSymbolAddress(&pw2h, g_w2h);
    cudaGetSymbolAddress(&pb1,  g_b1);
    cudaGetSymbolAddress(&pcmb, g_cmb);

    cudaFuncSetAttribute(psa_gemm1,
                         cudaFuncAttributeMaxDynamicSharedMemorySize, SMEM_G1);
    cudaFuncSetAttribute(psa_attn_proj,
                         cudaFuncAttributeMaxDynamicSharedMemorySize, SMEM_B);

    // 0) small prep (w1/w2/b1 only)
    psa_prep_small<<<257, 512>>>(q_w, kv_w, proj_w, q_b, kv_b);

    // 1) qkv16 = fp16( x @ [q_w*scale;kv_w]^T + b ); also builds cmb slices
    psa_gemm1<<<2048, 256, SMEM_G1>>>(
        x, (const __half*)pw1h, (const float*)pb1,
        bt, ri, mask, (__half*)pqkv);

    // 2) fused HMMA attention + out-projection (2 CTAs/SM)
    psa_attn_proj<<<4096, 256, SMEM_B>>>(
        (const __half*)pqkv, (const float*)pcmb,
        (const __half*)pw2h, proj_b, out);
}